// round 1
// baseline (speedup 1.0000x reference)
#include <cuda_runtime.h>
#include <math.h>

// Shapes (fixed for this problem)
#define BH   64      // H (query dim)
#define BD   64      // D (memory feature dim)
#define BM   2048    // M (memory slots)
#define BV   128     // V (vocab)
#define BG   32      // G (gate hidden)

// One CTA per batch element. 256 threads = 8 warps = 16 half-warp softmax states.
// Each half-warp processes one memory row (64 f32 = 256B) per iteration:
// lane covers 4 consecutive floats (float4), 16 lanes cover the row, coalesced.
// Online (flash-style) softmax: single pass over the 512KB memory slab per batch.
__global__ __launch_bounds__(256, 8) void memret_kernel(
    const float* __restrict__ query,   // (B,64)
    const float* __restrict__ memory,  // (B,2048,64)
    const float* __restrict__ Wq,      // (64,64)
    const float* __restrict__ bq,      // (64)
    const float* __restrict__ Wo,      // (64,64)
    const float* __restrict__ bo,      // (64)
    const float* __restrict__ Wg1,     // (65,32)
    const float* __restrict__ bg1,     // (32)
    const float* __restrict__ Wg2,     // (32,1)
    const float* __restrict__ bg2,     // (1)
    const float* __restrict__ nullv,   // (64)
    const float* __restrict__ Wc,      // (64,128)
    const float* __restrict__ bc,      // (128)
    float* __restrict__ out_logits,    // (B,128)
    float* __restrict__ out_gate)      // (B) or nullptr
{
    __shared__ float q_s[BH];          // query[b]
    __shared__ float qp_s[BD];         // q_proj
    __shared__ float m_s[16], l_s[16]; // per-state running max / sumexp
    __shared__ float acc_s[16][BD];    // per-state weighted accumulators
    __shared__ float ret_s[BD];        // retrieved
    __shared__ float reth_s[BH];       // retrieved @ Wo + bo
    __shared__ float g1_s[BG];         // gate hidden
    __shared__ float o_s[BH];          // gated output
    __shared__ float gate_sh;

    const int b   = blockIdx.x;
    const int tid = threadIdx.x;

    // ---- prologue: load query, compute q_proj = q @ Wq + bq ----
    if (tid < BH) q_s[tid] = query[(size_t)b * BH + tid];
    __syncthreads();
    if (tid < BD) {
        float acc = bq[tid];
        #pragma unroll
        for (int h = 0; h < BH; ++h) acc += q_s[h] * Wq[h * BD + tid];
        qp_s[tid] = acc;
    }
    __syncthreads();

    // ---- main loop: streaming online softmax over memory[b] ----
    const int lane = tid & 31;
    const int warp = tid >> 5;
    const int half = lane >> 4;     // 0/1: which half-warp
    const int hl   = lane & 15;     // lane within half-warp
    const float4 q4 = reinterpret_cast<const float4*>(qp_s)[hl];
    const float4* __restrict__ mrow =
        reinterpret_cast<const float4*>(memory + (size_t)b * (BM * BD));

    float  mmax = -INFINITY;
    float  lsum = 0.0f;
    float4 acc4 = make_float4(0.f, 0.f, 0.f, 0.f);
    const int rbase = warp * 2 + half;   // this state's row offset within each 16-row tile

    #pragma unroll 4
    for (int i = 0; i < BM / 16; ++i) {
        const int row = i * 16 + rbase;
        const float4 v = mrow[row * (BD / 4) + hl];
        float d = v.x * q4.x + v.y * q4.y + v.z * q4.z + v.w * q4.w;
        // reduce across the 16-lane half-warp (xor partners stay within the half)
        d += __shfl_xor_sync(0xffffffffu, d, 8);
        d += __shfl_xor_sync(0xffffffffu, d, 4);
        d += __shfl_xor_sync(0xffffffffu, d, 2);
        d += __shfl_xor_sync(0xffffffffu, d, 1);
        const float s  = d * 0.125f;            // / sqrt(64)
        const float nm = fmaxf(mmax, s);
        const float sc = __expf(mmax - nm);     // 1.0 when max unchanged
        const float p  = __expf(s - nm);
        lsum   = lsum * sc + p;
        acc4.x = acc4.x * sc + p * v.x;
        acc4.y = acc4.y * sc + p * v.y;
        acc4.z = acc4.z * sc + p * v.z;
        acc4.w = acc4.w * sc + p * v.w;
        mmax = nm;
    }

    // ---- merge 16 partial softmax states ----
    const int sidx = warp * 2 + half;
    if (hl == 0) { m_s[sidx] = mmax; l_s[sidx] = lsum; }
    acc_s[sidx][4 * hl + 0] = acc4.x;
    acc_s[sidx][4 * hl + 1] = acc4.y;
    acc_s[sidx][4 * hl + 2] = acc4.z;
    acc_s[sidx][4 * hl + 3] = acc4.w;
    __syncthreads();

    // every thread computes the global max / normalizer (16 values, cheap, no extra sync)
    float gmax = -INFINITY;
    #pragma unroll
    for (int s2 = 0; s2 < 16; ++s2) gmax = fmaxf(gmax, m_s[s2]);
    float L = 0.0f;
    #pragma unroll
    for (int s2 = 0; s2 < 16; ++s2) L += l_s[s2] * __expf(m_s[s2] - gmax);

    if (tid < BD) {
        float r = 0.0f;
        #pragma unroll
        for (int s2 = 0; s2 < 16; ++s2) r += acc_s[s2][tid] * __expf(m_s[s2] - gmax);
        ret_s[tid] = r / L;
    }
    __syncthreads();

    // ---- epilogue (tiny GEMVs; weights L2-resident across 2048 CTAs) ----
    // retrieved_h = retrieved @ Wo + bo   (threads 0..63)
    if (tid < BH) {
        float acc = bo[tid];
        #pragma unroll
        for (int d2 = 0; d2 < BD; ++d2) acc += ret_s[d2] * Wo[d2 * BH + tid];
        reth_s[tid] = acc;
    }
    // gate hidden = relu([q, max_sim] @ Wg1 + bg1)   (threads 64..95, in parallel)
    if (tid >= 64 && tid < 64 + BG) {
        const int j = tid - 64;
        float acc = bg1[j] + gmax * Wg1[BH * BG + j];   // row 64 = max_sim row; gmax == max_sim
        #pragma unroll
        for (int h = 0; h < BH; ++h) acc += q_s[h] * Wg1[h * BG + j];
        g1_s[j] = fmaxf(acc, 0.0f);
    }
    __syncthreads();

    if (tid == 0) {
        float z = bg2[0];
        #pragma unroll
        for (int j = 0; j < BG; ++j) z += g1_s[j] * Wg2[j];
        gate_sh = 1.0f / (1.0f + __expf(-z));
    }
    __syncthreads();

    const float gate = gate_sh;
    if (tid < BH) o_s[tid] = gate * reth_s[tid] + (1.0f - gate) * nullv[tid];
    __syncthreads();

    // logits = out @ Wc + bc   (threads 0..127)
    if (tid < BV) {
        float acc = bc[tid];
        #pragma unroll
        for (int h = 0; h < BH; ++h) acc += o_s[h] * Wc[h * BV + tid];
        out_logits[(size_t)b * BV + tid] = acc;
    }
    if (tid == 0 && out_gate != nullptr) out_gate[b] = gate;
}

extern "C" void kernel_launch(void* const* d_in, const int* in_sizes, int n_in,
                              void* d_out, int out_size) {
    // metadata order (setup_inputs insertion order):
    // 0 query, 1 memory, 2 Wq, 3 bq, 4 Wo, 5 bo, 6 Wg1, 7 bg1, 8 Wg2, 9 bg2,
    // 10 null_vec, 11 Wc, 12 bc
    const float* query  = (const float*)d_in[0];
    const float* memory = (const float*)d_in[1];
    const float* Wq  = (const float*)d_in[2];
    const float* bq  = (const float*)d_in[3];
    const float* Wo  = (const float*)d_in[4];
    const float* bo  = (const float*)d_in[5];
    const float* Wg1 = (const float*)d_in[6];
    const float* bg1 = (const float*)d_in[7];
    const float* Wg2 = (const float*)d_in[8];
    const float* bg2 = (const float*)d_in[9];
    const float* nullv = (const float*)d_in[10];
    const float* Wc  = (const float*)d_in[11];
    const float* bc  = (const float*)d_in[12];

    const int B = in_sizes[0] / BH;     // 2048
    float* out_logits = (float*)d_out;
    // Reference returns (logits, gate). If out buffer also holds gate, write it.
    float* out_gate = (out_size >= B * BV + B) ? (out_logits + (size_t)B * BV) : nullptr;

    memret_kernel<<<B, 256>>>(query, memory, Wq, bq, Wo, bo, Wg1, bg1, Wg2, bg2,
                              nullv, Wc, bc, out_logits, out_gate);
}